// round 14
// baseline (speedup 1.0000x reference)
#include <cuda_runtime.h>
#include <cuda_bf16.h>
#include <math.h>

// ---------------------------------------------------------------------------
// N=50000 nodes, IN_C=512, GAT1: 3 heads x 16, GAT2: 1 head x 128,
// GCN 128->128, Linear 128->128. E=800000 edges + N self loops.
// ---------------------------------------------------------------------------
#define NEG_SLOPE 0.2f
#define NMAX   50048
#define ETMAX  860160
typedef unsigned long long ull;

// ------------------------- scratch (device globals) -------------------------
__device__ int   g_is64;
__device__ __align__(16) int   g_degi[NMAX];
__device__ __align__(16) int   g_rp[NMAX + 8];
__device__ __align__(16) int   g_cur[NMAX + 8];
__device__ int   g_bsum[64], g_boff[64];
__device__ int   g_csrc[ETMAX];            // src node per CSR slot (sorted by dst)
__device__ __align__(16) float g_h1[NMAX*48];
__device__ __align__(16) float g_h1b[NMAX*48];   // split-K partial (slice 1)
__device__ float g_es1[NMAX*3], g_ed1[NMAX*3];
__device__ float g_acc1[NMAX*48];          // GAT1 out (post-ELU)
__device__ float g_h2[NMAX*128];
__device__ float g_es2[NMAX], g_ed2[NMAX];
__device__ float g_acc2[NMAX*128];         // GAT2 out (post log_softmax)
__device__ __align__(16) float g_dinv[NMAX];
__device__ float g_hg[NMAX*128];
__device__ float g_accg[NMAX*128];         // GCN out (post relu)

// ------------------------------- helpers ------------------------------------
__device__ __forceinline__ float leaky(float x) {
    return x > 0.0f ? x : NEG_SLOPE * x;
}
// exp without max-shift: logits analytically bounded ~|13|; clamp at 80
// (fp32 exp overflows at 88). softmax is shift-invariant.
__device__ __forceinline__ float expw(float x) {
    return __expf(fminf(x, 80.0f));
}

__device__ __forceinline__ ull pack2(float lo, float hi) {
    ull r;
    asm("mov.b64 %0, {%1, %2};" : "=l"(r)
        : "r"(__float_as_uint(lo)), "r"(__float_as_uint(hi)));
    return r;
}
__device__ __forceinline__ ull dup2(float f) {
    ull r;
    unsigned u = __float_as_uint(f);
    asm("mov.b64 %0, {%1, %1};" : "=l"(r) : "r"(u));
    return r;
}
__device__ __forceinline__ void fma2(ull& a, ull x, ull w) {
    asm("fma.rn.f32x2 %0, %1, %2, %0;" : "+l"(a) : "l"(x), "l"(w));
}
__device__ __forceinline__ void unpack2(ull v, float& lo, float& hi) {
    asm("mov.b64 {%0, %1}, %2;" : "=f"(lo), "=f"(hi) : "l"(v));
}

// pointer tag dispatch (no host-side symbol lookup)
// 0 = external, 1=g_acc1, 2=g_acc2, 3=g_accg, 11=g_h1, 12=g_h2, 13=g_hg
template<int SEL>
__device__ __forceinline__ float* sel_ptr(float* ext) {
    if      (SEL == 1)  return g_acc1;
    else if (SEL == 2)  return g_acc2;
    else if (SEL == 3)  return g_accg;
    else if (SEL == 11) return g_h1;
    else if (SEL == 12) return g_h2;
    else if (SEL == 13) return g_hg;
    else                return ext;
}

// ----------------------------- edge parsing ---------------------------------
__device__ __forceinline__ void parse_edge(const int* __restrict__ ei32, int is64,
                                           int e, int E, int n, int& s, int& d) {
    if (e < E) {
        if (is64) { s = ei32[2*(size_t)e]; d = ei32[2*((size_t)E + e)]; }
        else      { s = ei32[e];           d = ei32[(size_t)E + e]; }
    } else {
        s = d = e - E;
    }
    s = min(max(s, 0), n - 1);
    d = min(max(d, 0), n - 1);
}

// ------------------------------- CSR build ----------------------------------
// zero degree counters; thread 0 also detects edge dtype
__global__ void zero_deg(const int* __restrict__ ei32, int n) {
    int i = blockIdx.x * blockDim.x + threadIdx.x;
    if (i < n) g_degi[i] = 0;
    if (i == 0) {
        int all_hi_zero = 1;
        for (int k = 0; k < 64; k++) {
            if (ei32[2*k + 1] != 0) { all_hi_zero = 0; break; }
        }
        g_is64 = all_hi_zero;
    }
}

__global__ void count_deg(const int* __restrict__ ei32, int E, int n) {
    int e = blockIdx.x * blockDim.x + threadIdx.x;
    int ET = E + n;
    if (e < ET) {
        int s, d;
        parse_edge(ei32, g_is64, e, E, n, s, d);
        atomicAdd(&g_degi[d], 1);
    }
}

// multi-block scan: 2048 elems/block (256 thr x 8), <=32 blocks for n<=65536
__global__ void scan_block(int n) {
    int b = blockIdx.x, tid = threadIdx.x;
    int lane = tid & 31, wid = tid >> 5;
    int i0 = b*2048 + tid*8;
    int s = 0;
    if (i0 + 8 <= n) {
        int4 a = *(const int4*)&g_degi[i0];
        int4 c = *(const int4*)&g_degi[i0 + 4];
        s = a.x+a.y+a.z+a.w + c.x+c.y+c.z+c.w;
    } else {
        #pragma unroll
        for (int q = 0; q < 8; q++) if (i0 + q < n) s += g_degi[i0 + q];
    }
    #pragma unroll
    for (int o = 16; o > 0; o >>= 1) s += __shfl_xor_sync(0xffffffffu, s, o);
    __shared__ int ws[8];
    if (lane == 0) ws[wid] = s;
    __syncthreads();
    if (tid == 0) {
        int t = 0;
        #pragma unroll
        for (int j = 0; j < 8; j++) t += ws[j];
        g_bsum[b] = t;
    }
}

__global__ void scan_partials(int nb, int n) {
    int tid = threadIdx.x;                  // 1 warp
    int v = (tid < nb) ? g_bsum[tid] : 0;
    int incl = v;
    #pragma unroll
    for (int o = 1; o < 32; o <<= 1) {
        int t = __shfl_up_sync(0xffffffffu, incl, o);
        if (tid >= o) incl += t;
    }
    if (tid < nb) g_boff[tid] = incl - v;
    if (tid == 31) g_rp[n] = incl;          // grand total
}

__global__ void scan_apply(int n) {
    int b = blockIdx.x, tid = threadIdx.x;
    int lane = tid & 31, wid = tid >> 5;
    int i0 = b*2048 + tid*8;
    int v[8];
    if (i0 + 8 <= n) {
        int4 a = *(const int4*)&g_degi[i0];
        int4 c = *(const int4*)&g_degi[i0 + 4];
        v[0]=a.x; v[1]=a.y; v[2]=a.z; v[3]=a.w;
        v[4]=c.x; v[5]=c.y; v[6]=c.z; v[7]=c.w;
    } else {
        #pragma unroll
        for (int q = 0; q < 8; q++) v[q] = (i0 + q < n) ? g_degi[i0 + q] : 0;
    }
    int tsum = 0;
    #pragma unroll
    for (int q = 0; q < 8; q++) tsum += v[q];
    int incl = tsum;
    #pragma unroll
    for (int o = 1; o < 32; o <<= 1) {
        int t = __shfl_up_sync(0xffffffffu, incl, o);
        if (lane >= o) incl += t;
    }
    __shared__ int ws[8], woff[8];
    if (lane == 31) ws[wid] = incl;
    __syncthreads();
    if (tid < 8) {
        int t = 0;
        for (int j = 0; j < tid; j++) t += ws[j];
        woff[tid] = t;
    }
    __syncthreads();
    int run = g_boff[b] + woff[wid] + (incl - tsum);
    if (i0 + 8 <= n) {
        int rp[8]; float dv[8];
        #pragma unroll
        for (int q = 0; q < 8; q++) {
            rp[q] = run; run += v[q];
            dv[q] = rsqrtf(fmaxf((float)v[q], 1.0f));
        }
        *(int4*)&g_rp[i0]      = make_int4(rp[0], rp[1], rp[2], rp[3]);
        *(int4*)&g_rp[i0 + 4]  = make_int4(rp[4], rp[5], rp[6], rp[7]);
        *(int4*)&g_cur[i0]     = make_int4(rp[0], rp[1], rp[2], rp[3]);
        *(int4*)&g_cur[i0 + 4] = make_int4(rp[4], rp[5], rp[6], rp[7]);
        *(float4*)&g_dinv[i0]     = make_float4(dv[0], dv[1], dv[2], dv[3]);
        *(float4*)&g_dinv[i0 + 4] = make_float4(dv[4], dv[5], dv[6], dv[7]);
    } else {
        #pragma unroll
        for (int q = 0; q < 8; q++) {
            int i = i0 + q;
            if (i < n) {
                g_rp[i] = run; g_cur[i] = run;
                g_dinv[i] = rsqrtf(fmaxf((float)v[q], 1.0f));
            }
            run += v[q];
        }
    }
}

__global__ void fill_csr(const int* __restrict__ ei32, int E, int n) {
    int e = blockIdx.x * blockDim.x + threadIdx.x;
    int ET = E + n;
    if (e < ET) {
        int s, d;
        parse_edge(ei32, g_is64, e, E, n, s, d);
        int pos = atomicAdd(&g_cur[d], 1);
        g_csrc[pos] = s;
    }
}

// ------------------------------ GEMM ----------------------------------------
// C[M,NC] = A[M,K] @ W[K,NC] (+bias). Per-thread tile 8 rows x CT cols.
// Xs transposed [k][row]; row pairs packed as f32x2 for fma.rn.f32x2.
// (R10 inner loop -- measured fastest; do not alter.)
// CT=8 uses a permuted W smem layout. KSPLIT=2: slice 0 -> C, slice 1 -> g_h1b.
template<int K, int NC, int BM, int BK, int CT, int KSPLIT, int ASEL, int CSEL>
__global__ void gemm_kernel(const float* __restrict__ Aext, const float* __restrict__ W,
                            const float* __restrict__ bias, float* __restrict__ Cext, int M) {
    constexpr int CTN = NC / CT;           // col groups
    constexpr int RTN = BM / 8;            // row groups
    constexpr int THREADS = CTN * RTN;
    constexpr int KLEN = K / KSPLIT;
    __shared__ __align__(16) float Xs[BK][BM + 4];
    __shared__ __align__(16) float Wsh[BK][NC];

    const float* A = sel_ptr<ASEL>((float*)Aext);
    float*       C = sel_ptr<CSEL>(Cext);

    int tid  = threadIdx.x;
    int ct   = tid % CTN;
    int rt   = tid / CTN;
    int r0   = rt * 8;
    int kslice = blockIdx.x % KSPLIT;
    int row0 = (blockIdx.x / KSPLIT) * BM;
    int koff = kslice * KLEN;
    if (KSPLIT > 1 && kslice == 1) C = g_h1b;

    ull acc[4][CT];
    #pragma unroll
    for (int p = 0; p < 4; p++)
        #pragma unroll
        for (int c = 0; c < CT; c++) acc[p][c] = 0ULL;

    for (int kc0 = koff; kc0 < koff + KLEN; kc0 += BK) {
        // W chunk (permuted layout for CT=8)
        for (int idx = tid; idx < BK*(NC/4); idx += THREADS) {
            int k = idx / (NC/4), cq = idx % (NC/4);
            float4 v = *(const float4*)&W[(size_t)(kc0 + k)*NC + cq*4];
            int pos = (CT == 8) ? ((cq & 1)*(NC/2) + (cq >> 1)*4) : cq*4;
            *(float4*)&Wsh[k][pos] = v;
        }
        // X chunk, transposed store
        for (int idx = tid; idx < BM*(BK/4); idx += THREADS) {
            int r = idx / (BK/4), kq = idx % (BK/4);
            int gr = row0 + r;
            float4 v = make_float4(0.f, 0.f, 0.f, 0.f);
            if (gr < M) v = *(const float4*)&A[(size_t)gr*K + kc0 + kq*4];
            Xs[kq*4+0][r] = v.x;
            Xs[kq*4+1][r] = v.y;
            Xs[kq*4+2][r] = v.z;
            Xs[kq*4+3][r] = v.w;
        }
        __syncthreads();

        #pragma unroll 2
        for (int kk = 0; kk < BK; kk++) {
            float4 xa = *(const float4*)&Xs[kk][r0];
            float4 xb = *(const float4*)&Xs[kk][r0+4];
            ull xp[4];
            xp[0] = pack2(xa.x, xa.y);
            xp[1] = pack2(xa.z, xa.w);
            xp[2] = pack2(xb.x, xb.y);
            xp[3] = pack2(xb.z, xb.w);
            ull wp[CT];
            float4 w0 = *(const float4*)&Wsh[kk][ct*4];
            wp[0] = dup2(w0.x); wp[1] = dup2(w0.y);
            wp[2] = dup2(w0.z); wp[3] = dup2(w0.w);
            if (CT == 8) {
                float4 w1 = *(const float4*)&Wsh[kk][NC/2 + ct*4];
                wp[4] = dup2(w1.x); wp[5] = dup2(w1.y);
                wp[6] = dup2(w1.z); wp[7] = dup2(w1.w);
            }
            #pragma unroll
            for (int p = 0; p < 4; p++)
                #pragma unroll
                for (int c = 0; c < CT; c++)
                    fma2(acc[p][c], xp[p], wp[c]);
        }
        __syncthreads();
    }

    // epilogue: plain float4 stores (split-K slices write disjoint buffers)
    int c0 = ct * CT;
    float bv[CT];
    #pragma unroll
    for (int c = 0; c < CT; c++) bv[c] = bias ? bias[c0 + c] : 0.f;
    #pragma unroll
    for (int p = 0; p < 4; p++) {
        float lo[CT], hi[CT];
        #pragma unroll
        for (int c = 0; c < CT; c++) {
            unpack2(acc[p][c], lo[c], hi[c]);
            lo[c] += bv[c]; hi[c] += bv[c];
        }
        int gr0 = row0 + r0 + 2*p;
        if (gr0 < M) {
            #pragma unroll
            for (int cq = 0; cq < CT/4; cq++)
                *(float4*)&C[(size_t)gr0*NC + c0 + cq*4] =
                    make_float4(lo[cq*4], lo[cq*4+1], lo[cq*4+2], lo[cq*4+3]);
        }
        if (gr0 + 1 < M) {
            #pragma unroll
            for (int cq = 0; cq < CT/4; cq++)
                *(float4*)&C[(size_t)(gr0+1)*NC + c0 + cq*4] =
                    make_float4(hi[cq*4], hi[cq*4+1], hi[cq*4+2], hi[cq*4+3]);
        }
    }
}

// ------------------------------ GAT layer 1 ---------------------------------
// fused: h1 = h1_partial0 + h1_partial1 (written back), then per-(node,head)
// attention logits es/ed.
__global__ void logits1_fused(const float* __restrict__ a_src, const float* __restrict__ a_dst, int n) {
    int i = blockIdx.x * blockDim.x + threadIdx.x;
    if (i < n*3) {
        int node = i / 3, h = i % 3;
        size_t base = (size_t)node*48 + h*16;
        float as[16];
        #pragma unroll
        for (int q = 0; q < 4; q++) {
            float4 a = *(const float4*)&g_h1[base + q*4];
            float4 b = *(const float4*)&g_h1b[base + q*4];
            float4 v = make_float4(a.x+b.x, a.y+b.y, a.z+b.z, a.w+b.w);
            *(float4*)&g_h1[base + q*4] = v;
            as[q*4+0]=v.x; as[q*4+1]=v.y; as[q*4+2]=v.z; as[q*4+3]=v.w;
        }
        float s = 0.f, d = 0.f;
        #pragma unroll
        for (int c = 0; c < 16; c++) {
            s += as[c] * a_src[h*16 + c];
            d += as[c] * a_dst[h*16 + c];
        }
        g_es1[i] = s;
        g_ed1[i] = d;
    }
}

// warp per node: softmax-attention aggregation (no max pass; see expw),
// fused norm + bias + ELU. Edge loop unrolled x2 for MLP.
__global__ void gat1_agg(const float* __restrict__ b1, int n) {
    int gw = (blockIdx.x * blockDim.x + threadIdx.x) >> 5;
    int lane = threadIdx.x & 31;
    if (gw >= n) return;
    int d = gw;
    int rp0 = g_rp[d], cnt = g_rp[d+1] - rp0;
    float ed0 = g_ed1[d*3+0], ed1 = g_ed1[d*3+1], ed2 = g_ed1[d*3+2];

    int ha = lane >> 4;
    float eda = ha ? ed1 : ed0;
    float acca = 0.f, accb = 0.f, ssa = 0.f, ssb = 0.f;
    int p = rp0, pend = rp0 + cnt;
    for (; p + 2 <= pend; p += 2) {
        int s0 = g_csrc[p], s1 = g_csrc[p+1];
        float la0 = g_es1[s0*3+ha], la1 = g_es1[s1*3+ha];
        float h0 = g_h1[s0*48 + lane], h1v = g_h1[s1*48 + lane];
        float wa0 = expw(leaky(la0 + eda));
        float wa1 = expw(leaky(la1 + eda));
        ssa += wa0 + wa1;
        acca += wa0 * h0 + wa1 * h1v;
        if (lane < 16) {
            float lb0 = g_es1[s0*3+2], lb1 = g_es1[s1*3+2];
            float hb0 = g_h1[s0*48 + 32 + lane], hb1 = g_h1[s1*48 + 32 + lane];
            float wb0 = expw(leaky(lb0 + ed2));
            float wb1 = expw(leaky(lb1 + ed2));
            ssb += wb0 + wb1;
            accb += wb0 * hb0 + wb1 * hb1;
        }
    }
    if (p < pend) {
        int s0 = g_csrc[p];
        float wa = expw(leaky(g_es1[s0*3+ha] + eda));
        ssa += wa;
        acca += wa * g_h1[s0*48 + lane];
        if (lane < 16) {
            float wb = expw(leaky(g_es1[s0*3+2] + ed2));
            ssb += wb;
            accb += wb * g_h1[s0*48 + 32 + lane];
        }
    }
    float va = acca / ssa + b1[lane];
    va = va > 0.f ? va : expm1f(va);
    g_acc1[d*48 + lane] = va;
    if (lane < 16) {
        float vb = accb / ssb + b1[32 + lane];
        vb = vb > 0.f ? vb : expm1f(vb);
        g_acc1[d*48 + 32 + lane] = vb;
    }
}

// ------------------------------ GAT layer 2 ---------------------------------
// one warp per node, float4 per lane (lane q covers channels 4q..4q+3)
__global__ void logits2(const float* __restrict__ a_src, const float* __restrict__ a_dst, int n) {
    int gid = blockIdx.x * blockDim.x + threadIdx.x;
    int node = gid >> 5;
    int lane = gid & 31;
    if (node < n) {
        float4 hv = *(const float4*)&g_h2[(size_t)node*128 + lane*4];
        float4 av = *(const float4*)&a_src[lane*4];
        float4 dv = *(const float4*)&a_dst[lane*4];
        float s = hv.x*av.x + hv.y*av.y + hv.z*av.z + hv.w*av.w;
        float d = hv.x*dv.x + hv.y*dv.y + hv.z*dv.z + hv.w*dv.w;
        #pragma unroll
        for (int o = 16; o > 0; o >>= 1) {
            s += __shfl_xor_sync(0xffffffffu, s, o);
            d += __shfl_xor_sync(0xffffffffu, d, o);
        }
        if (lane == 0) { g_es2[node] = s; g_ed2[node] = d; }
    }
}

// warp per node: GAT2 aggregation (no max pass) fused with bias +
// log_softmax(128), unroll x2
__global__ void gat2_agg(const float* __restrict__ b2, int n) {
    int gw = (blockIdx.x * blockDim.x + threadIdx.x) >> 5;
    int lane = threadIdx.x & 31;
    if (gw >= n) return;
    int d = gw;
    int rp0 = g_rp[d], cnt = g_rp[d+1] - rp0;
    float edv = g_ed2[d];

    float acc[4] = {0.f, 0.f, 0.f, 0.f};
    float ss = 0.f;
    int p = rp0, pend = rp0 + cnt;
    for (; p + 2 <= pend; p += 2) {
        int s0 = g_csrc[p], s1 = g_csrc[p+1];
        float e0 = g_es2[s0], e1 = g_es2[s1];
        const float* hp0 = g_h2 + (size_t)s0*128 + lane;
        const float* hp1 = g_h2 + (size_t)s1*128 + lane;
        float h0[4], h1[4];
        #pragma unroll
        for (int q = 0; q < 4; q++) { h0[q] = hp0[q*32]; h1[q] = hp1[q*32]; }
        float w0 = expw(leaky(e0 + edv));
        float w1 = expw(leaky(e1 + edv));
        ss += w0 + w1;
        #pragma unroll
        for (int q = 0; q < 4; q++) acc[q] += w0 * h0[q] + w1 * h1[q];
    }
    if (p < pend) {
        int s0 = g_csrc[p];
        float w = expw(leaky(g_es2[s0] + edv));
        ss += w;
        const float* hp = g_h2 + (size_t)s0*128 + lane;
        #pragma unroll
        for (int q = 0; q < 4; q++) acc[q] += w * hp[q*32];
    }

    float v[4];
    float inv = 1.0f / ss;
    #pragma unroll
    for (int q = 0; q < 4; q++) v[q] = acc[q] * inv + b2[lane + q*32];

    float lm = fmaxf(fmaxf(v[0], v[1]), fmaxf(v[2], v[3]));
    #pragma unroll
    for (int o = 16; o > 0; o >>= 1) lm = fmaxf(lm, __shfl_xor_sync(0xffffffffu, lm, o));
    float es = 0.f;
    #pragma unroll
    for (int q = 0; q < 4; q++) es += __expf(v[q] - lm);
    #pragma unroll
    for (int o = 16; o > 0; o >>= 1) es += __shfl_xor_sync(0xffffffffu, es, o);
    float lse = lm + logf(es);
    float* op = g_acc2 + (size_t)d*128 + lane;
    #pragma unroll
    for (int q = 0; q < 4; q++) op[q*32] = v[q] - lse;
}

// ------------------------------- GCN ----------------------------------------
// warp per node: normalized aggregation fused with bias + relu, unroll x2
__global__ void gcn_agg(const float* __restrict__ bg, int n) {
    int gw = (blockIdx.x * blockDim.x + threadIdx.x) >> 5;
    int lane = threadIdx.x & 31;
    if (gw >= n) return;
    int d = gw;
    int rp0 = g_rp[d], cnt = g_rp[d+1] - rp0;
    float dd = g_dinv[d];

    float acc[4] = {0.f, 0.f, 0.f, 0.f};
    int p = rp0, pend = rp0 + cnt;
    for (; p + 2 <= pend; p += 2) {
        int s0 = g_csrc[p], s1 = g_csrc[p+1];
        float n0 = g_dinv[s0] * dd, n1 = g_dinv[s1] * dd;
        const float* hp0 = g_hg + (size_t)s0*128 + lane;
        const float* hp1 = g_hg + (size_t)s1*128 + lane;
        float h0[4], h1[4];
        #pragma unroll
        for (int q = 0; q < 4; q++) { h0[q] = hp0[q*32]; h1[q] = hp1[q*32]; }
        #pragma unroll
        for (int q = 0; q < 4; q++) acc[q] += n0 * h0[q] + n1 * h1[q];
    }
    if (p < pend) {
        int s0 = g_csrc[p];
        float nrm = g_dinv[s0] * dd;
        const float* hp = g_hg + (size_t)s0*128 + lane;
        #pragma unroll
        for (int q = 0; q < 4; q++) acc[q] += nrm * hp[q*32];
    }
    float* op = g_accg + (size_t)d*128 + lane;
    #pragma unroll
    for (int q = 0; q < 4; q++) {
        float v = acc[q] + bg[lane + q*32];
        op[q*32] = v > 0.f ? v : 0.f;
    }
}

// ------------------------------ launch --------------------------------------
static inline int cdiv(int a, int b) { return (a + b - 1) / b; }

extern "C" void kernel_launch(void* const* d_in, const int* in_sizes, int n_in,
                              void* d_out, int out_size) {
    const float* x   = (const float*)d_in[0];
    const int*   ei  = (const int*)d_in[1];   // int32 view; dtype detected on device
    const float* W1  = (const float*)d_in[2];
    const float* as1 = (const float*)d_in[3];
    const float* ad1 = (const float*)d_in[4];
    const float* b1  = (const float*)d_in[5];
    const float* W2  = (const float*)d_in[6];
    const float* as2 = (const float*)d_in[7];
    const float* ad2 = (const float*)d_in[8];
    const float* b2  = (const float*)d_in[9];
    const float* Wg  = (const float*)d_in[10];
    const float* bg  = (const float*)d_in[11];
    const float* Wl  = (const float*)d_in[12];
    const float* bl  = (const float*)d_in[13];
    float*       out = (float*)d_out;

    int n  = in_sizes[0] / 512;
    int E  = in_sizes[1] / 2;
    int ET = E + n;
    if (ET > ETMAX) ET = ETMAX;

    int warps_grid = cdiv(n * 32, 256);
    int nb = cdiv(n, 2048);                   // scan blocks (25 for n=50000)

    zero_deg<<<cdiv(n,256),256>>>(ei, n);             // 1 (also dtype detect)
    count_deg<<<cdiv(ET,256),256>>>(ei, E, n);        // 2
    scan_block<<<nb,256>>>(n);                        // 3

    // GAT1 GEMM as 4th launch (ncu profiles launch #4)
    // CT=4 (192 thr), BK=32 (23KB smem -> 5 blocks/SM), split-K x2
    gemm_kernel<512,48,128,32,4,2, 0,11><<<2*cdiv(n,128),192>>>(x, W1, nullptr, nullptr, n); // 4

    scan_partials<<<1,32>>>(nb, n);                   // 5
    scan_apply<<<nb,256>>>(n);                        // 6
    fill_csr<<<cdiv(ET,256),256>>>(ei, E, n);         // 7

    // --- GAT layer 1 (fused partial-reduce + logits) ---
    logits1_fused<<<cdiv(3*n,256),256>>>(as1, ad1, n);
    gat1_agg<<<warps_grid,256>>>(b1, n);

    // --- GAT layer 2 (+ log_softmax) ---
    gemm_kernel<48,128,64,48,8,1, 1,12><<<cdiv(n,64),128>>>(nullptr, W2, nullptr, nullptr, n);
    logits2<<<cdiv(32*n,256),256>>>(as2, ad2, n);
    gat2_agg<<<warps_grid,256>>>(b2, n);

    // --- GCN + relu (BK 32->64: half the sync count) ---
    gemm_kernel<128,128,64,64,8,1, 2,13><<<cdiv(n,64),128>>>(nullptr, Wg, nullptr, nullptr, n);
    gcn_agg<<<warps_grid,256>>>(bg, n);

    // --- final linear (BK 32->64) ---
    gemm_kernel<128,128,64,64,8,1, 3,0><<<cdiv(n,64),128>>>(nullptr, Wl, bl, out, n);
}

// round 16
// speedup vs baseline: 1.0374x; 1.0374x over previous
#include <cuda_runtime.h>
#include <cuda_bf16.h>
#include <math.h>

// ---------------------------------------------------------------------------
// N=50000 nodes, IN_C=512, GAT1: 3 heads x 16, GAT2: 1 head x 128,
// GCN 128->128, Linear 128->128. E=800000 edges + N self loops.
// ---------------------------------------------------------------------------
#define NEG_SLOPE 0.2f
#define NMAX   50048
#define ETMAX  860160
typedef unsigned long long ull;

// ------------------------- scratch (device globals) -------------------------
__device__ int   g_is64;
__device__ __align__(16) int   g_degi[NMAX];
__device__ __align__(16) int   g_rp[NMAX + 8];
__device__ __align__(16) int   g_cur[NMAX + 8];
__device__ int   g_bsum[64], g_boff[64];
__device__ int   g_csrc[ETMAX];            // src node per CSR slot (sorted by dst)
__device__ __align__(16) float g_h1[NMAX*48];
__device__ __align__(16) float g_h1b[NMAX*48];   // split-K partial (slice 1)
__device__ float g_es1[NMAX*3], g_ed1[NMAX*3];
__device__ float g_acc1[NMAX*48];          // GAT1 out (post-ELU)
__device__ float g_h2[NMAX*128];
__device__ float g_es2[NMAX], g_ed2[NMAX];
__device__ float g_acc2[NMAX*128];         // GAT2 out (post log_softmax)
__device__ __align__(16) float g_dinv[NMAX];
__device__ float g_hg[NMAX*128];
__device__ float g_accg[NMAX*128];         // GCN out (post relu)

// ------------------------------- helpers ------------------------------------
__device__ __forceinline__ float leaky(float x) {
    return x > 0.0f ? x : NEG_SLOPE * x;
}
// exp without max-shift: logits analytically bounded ~|13|; clamp at 80
// (fp32 exp overflows at 88). softmax is shift-invariant.
__device__ __forceinline__ float expw(float x) {
    return __expf(fminf(x, 80.0f));
}

__device__ __forceinline__ ull pack2(float lo, float hi) {
    ull r;
    asm("mov.b64 %0, {%1, %2};" : "=l"(r)
        : "r"(__float_as_uint(lo)), "r"(__float_as_uint(hi)));
    return r;
}
__device__ __forceinline__ ull dup2(float f) {
    ull r;
    unsigned u = __float_as_uint(f);
    asm("mov.b64 %0, {%1, %1};" : "=l"(r) : "r"(u));
    return r;
}
__device__ __forceinline__ void fma2(ull& a, ull x, ull w) {
    asm("fma.rn.f32x2 %0, %1, %2, %0;" : "+l"(a) : "l"(x), "l"(w));
}
__device__ __forceinline__ void unpack2(ull v, float& lo, float& hi) {
    asm("mov.b64 {%0, %1}, %2;" : "=f"(lo), "=f"(hi) : "l"(v));
}

// pointer tag dispatch (no host-side symbol lookup)
// 0 = external, 1=g_acc1, 2=g_acc2, 3=g_accg, 11=g_h1, 12=g_h2, 13=g_hg
template<int SEL>
__device__ __forceinline__ float* sel_ptr(float* ext) {
    if      (SEL == 1)  return g_acc1;
    else if (SEL == 2)  return g_acc2;
    else if (SEL == 3)  return g_accg;
    else if (SEL == 11) return g_h1;
    else if (SEL == 12) return g_h2;
    else if (SEL == 13) return g_hg;
    else                return ext;
}

// ----------------------------- edge parsing ---------------------------------
__device__ __forceinline__ void parse_edge(const int* __restrict__ ei32, int is64,
                                           int e, int E, int n, int& s, int& d) {
    if (e < E) {
        if (is64) { s = ei32[2*(size_t)e]; d = ei32[2*((size_t)E + e)]; }
        else      { s = ei32[e];           d = ei32[(size_t)E + e]; }
    } else {
        s = d = e - E;
    }
    s = min(max(s, 0), n - 1);
    d = min(max(d, 0), n - 1);
}

// ------------------------------- CSR build ----------------------------------
// zero degree counters; thread 0 also detects edge dtype
__global__ void zero_deg(const int* __restrict__ ei32, int n) {
    int i = blockIdx.x * blockDim.x + threadIdx.x;
    if (i < n) g_degi[i] = 0;
    if (i == 0) {
        int all_hi_zero = 1;
        for (int k = 0; k < 64; k++) {
            if (ei32[2*k + 1] != 0) { all_hi_zero = 0; break; }
        }
        g_is64 = all_hi_zero;
    }
}

__global__ void count_deg(const int* __restrict__ ei32, int E, int n) {
    int e = blockIdx.x * blockDim.x + threadIdx.x;
    int ET = E + n;
    if (e < ET) {
        int s, d;
        parse_edge(ei32, g_is64, e, E, n, s, d);
        atomicAdd(&g_degi[d], 1);
    }
}

// multi-block scan: 2048 elems/block (256 thr x 8), <=32 blocks for n<=65536
__global__ void scan_block(int n) {
    int b = blockIdx.x, tid = threadIdx.x;
    int lane = tid & 31, wid = tid >> 5;
    int i0 = b*2048 + tid*8;
    int s = 0;
    if (i0 + 8 <= n) {
        int4 a = *(const int4*)&g_degi[i0];
        int4 c = *(const int4*)&g_degi[i0 + 4];
        s = a.x+a.y+a.z+a.w + c.x+c.y+c.z+c.w;
    } else {
        #pragma unroll
        for (int q = 0; q < 8; q++) if (i0 + q < n) s += g_degi[i0 + q];
    }
    #pragma unroll
    for (int o = 16; o > 0; o >>= 1) s += __shfl_xor_sync(0xffffffffu, s, o);
    __shared__ int ws[8];
    if (lane == 0) ws[wid] = s;
    __syncthreads();
    if (tid == 0) {
        int t = 0;
        #pragma unroll
        for (int j = 0; j < 8; j++) t += ws[j];
        g_bsum[b] = t;
    }
}

__global__ void scan_partials(int nb, int n) {
    int tid = threadIdx.x;                  // 1 warp
    int v = (tid < nb) ? g_bsum[tid] : 0;
    int incl = v;
    #pragma unroll
    for (int o = 1; o < 32; o <<= 1) {
        int t = __shfl_up_sync(0xffffffffu, incl, o);
        if (tid >= o) incl += t;
    }
    if (tid < nb) g_boff[tid] = incl - v;
    if (tid == 31) g_rp[n] = incl;          // grand total
}

__global__ void scan_apply(int n) {
    int b = blockIdx.x, tid = threadIdx.x;
    int lane = tid & 31, wid = tid >> 5;
    int i0 = b*2048 + tid*8;
    int v[8];
    if (i0 + 8 <= n) {
        int4 a = *(const int4*)&g_degi[i0];
        int4 c = *(const int4*)&g_degi[i0 + 4];
        v[0]=a.x; v[1]=a.y; v[2]=a.z; v[3]=a.w;
        v[4]=c.x; v[5]=c.y; v[6]=c.z; v[7]=c.w;
    } else {
        #pragma unroll
        for (int q = 0; q < 8; q++) v[q] = (i0 + q < n) ? g_degi[i0 + q] : 0;
    }
    int tsum = 0;
    #pragma unroll
    for (int q = 0; q < 8; q++) tsum += v[q];
    int incl = tsum;
    #pragma unroll
    for (int o = 1; o < 32; o <<= 1) {
        int t = __shfl_up_sync(0xffffffffu, incl, o);
        if (lane >= o) incl += t;
    }
    __shared__ int ws[8], woff[8];
    if (lane == 31) ws[wid] = incl;
    __syncthreads();
    if (tid < 8) {
        int t = 0;
        for (int j = 0; j < tid; j++) t += ws[j];
        woff[tid] = t;
    }
    __syncthreads();
    int run = g_boff[b] + woff[wid] + (incl - tsum);
    if (i0 + 8 <= n) {
        int rp[8]; float dv[8];
        #pragma unroll
        for (int q = 0; q < 8; q++) {
            rp[q] = run; run += v[q];
            dv[q] = rsqrtf(fmaxf((float)v[q], 1.0f));
        }
        *(int4*)&g_rp[i0]      = make_int4(rp[0], rp[1], rp[2], rp[3]);
        *(int4*)&g_rp[i0 + 4]  = make_int4(rp[4], rp[5], rp[6], rp[7]);
        *(int4*)&g_cur[i0]     = make_int4(rp[0], rp[1], rp[2], rp[3]);
        *(int4*)&g_cur[i0 + 4] = make_int4(rp[4], rp[5], rp[6], rp[7]);
        *(float4*)&g_dinv[i0]     = make_float4(dv[0], dv[1], dv[2], dv[3]);
        *(float4*)&g_dinv[i0 + 4] = make_float4(dv[4], dv[5], dv[6], dv[7]);
    } else {
        #pragma unroll
        for (int q = 0; q < 8; q++) {
            int i = i0 + q;
            if (i < n) {
                g_rp[i] = run; g_cur[i] = run;
                g_dinv[i] = rsqrtf(fmaxf((float)v[q], 1.0f));
            }
            run += v[q];
        }
    }
}

__global__ void fill_csr(const int* __restrict__ ei32, int E, int n) {
    int e = blockIdx.x * blockDim.x + threadIdx.x;
    int ET = E + n;
    if (e < ET) {
        int s, d;
        parse_edge(ei32, g_is64, e, E, n, s, d);
        int pos = atomicAdd(&g_cur[d], 1);
        g_csrc[pos] = s;
    }
}

// ------------------------------ GEMM ----------------------------------------
// C[M,NC] = A[M,K] @ W[K,NC] (+bias). Per-thread tile 8 rows x CT cols.
// Xs transposed [k][row]; row pairs packed as f32x2 for fma.rn.f32x2.
// (R10 inner loop -- measured fastest; do not alter.)
// CT=8 uses a permuted W smem layout. KSPLIT=2: slice 0 -> C, slice 1 -> g_h1b.
template<int K, int NC, int BM, int BK, int CT, int KSPLIT, int ASEL, int CSEL>
__global__ void gemm_kernel(const float* __restrict__ Aext, const float* __restrict__ W,
                            const float* __restrict__ bias, float* __restrict__ Cext, int M) {
    constexpr int CTN = NC / CT;           // col groups
    constexpr int RTN = BM / 8;            // row groups
    constexpr int THREADS = CTN * RTN;
    constexpr int KLEN = K / KSPLIT;
    __shared__ __align__(16) float Xs[BK][BM + 4];
    __shared__ __align__(16) float Wsh[BK][NC];

    const float* A = sel_ptr<ASEL>((float*)Aext);
    float*       C = sel_ptr<CSEL>(Cext);

    int tid  = threadIdx.x;
    int ct   = tid % CTN;
    int rt   = tid / CTN;
    int r0   = rt * 8;
    int kslice = blockIdx.x % KSPLIT;
    int row0 = (blockIdx.x / KSPLIT) * BM;
    int koff = kslice * KLEN;
    if (KSPLIT > 1 && kslice == 1) C = g_h1b;

    ull acc[4][CT];
    #pragma unroll
    for (int p = 0; p < 4; p++)
        #pragma unroll
        for (int c = 0; c < CT; c++) acc[p][c] = 0ULL;

    for (int kc0 = koff; kc0 < koff + KLEN; kc0 += BK) {
        // W chunk (permuted layout for CT=8)
        for (int idx = tid; idx < BK*(NC/4); idx += THREADS) {
            int k = idx / (NC/4), cq = idx % (NC/4);
            float4 v = *(const float4*)&W[(size_t)(kc0 + k)*NC + cq*4];
            int pos = (CT == 8) ? ((cq & 1)*(NC/2) + (cq >> 1)*4) : cq*4;
            *(float4*)&Wsh[k][pos] = v;
        }
        // X chunk, transposed store
        for (int idx = tid; idx < BM*(BK/4); idx += THREADS) {
            int r = idx / (BK/4), kq = idx % (BK/4);
            int gr = row0 + r;
            float4 v = make_float4(0.f, 0.f, 0.f, 0.f);
            if (gr < M) v = *(const float4*)&A[(size_t)gr*K + kc0 + kq*4];
            Xs[kq*4+0][r] = v.x;
            Xs[kq*4+1][r] = v.y;
            Xs[kq*4+2][r] = v.z;
            Xs[kq*4+3][r] = v.w;
        }
        __syncthreads();

        #pragma unroll 2
        for (int kk = 0; kk < BK; kk++) {
            float4 xa = *(const float4*)&Xs[kk][r0];
            float4 xb = *(const float4*)&Xs[kk][r0+4];
            ull xp[4];
            xp[0] = pack2(xa.x, xa.y);
            xp[1] = pack2(xa.z, xa.w);
            xp[2] = pack2(xb.x, xb.y);
            xp[3] = pack2(xb.z, xb.w);
            ull wp[CT];
            float4 w0 = *(const float4*)&Wsh[kk][ct*4];
            wp[0] = dup2(w0.x); wp[1] = dup2(w0.y);
            wp[2] = dup2(w0.z); wp[3] = dup2(w0.w);
            if (CT == 8) {
                float4 w1 = *(const float4*)&Wsh[kk][NC/2 + ct*4];
                wp[4] = dup2(w1.x); wp[5] = dup2(w1.y);
                wp[6] = dup2(w1.z); wp[7] = dup2(w1.w);
            }
            #pragma unroll
            for (int p = 0; p < 4; p++)
                #pragma unroll
                for (int c = 0; c < CT; c++)
                    fma2(acc[p][c], xp[p], wp[c]);
        }
        __syncthreads();
    }

    // epilogue: plain float4 stores (split-K slices write disjoint buffers)
    int c0 = ct * CT;
    float bv[CT];
    #pragma unroll
    for (int c = 0; c < CT; c++) bv[c] = bias ? bias[c0 + c] : 0.f;
    #pragma unroll
    for (int p = 0; p < 4; p++) {
        float lo[CT], hi[CT];
        #pragma unroll
        for (int c = 0; c < CT; c++) {
            unpack2(acc[p][c], lo[c], hi[c]);
            lo[c] += bv[c]; hi[c] += bv[c];
        }
        int gr0 = row0 + r0 + 2*p;
        if (gr0 < M) {
            #pragma unroll
            for (int cq = 0; cq < CT/4; cq++)
                *(float4*)&C[(size_t)gr0*NC + c0 + cq*4] =
                    make_float4(lo[cq*4], lo[cq*4+1], lo[cq*4+2], lo[cq*4+3]);
        }
        if (gr0 + 1 < M) {
            #pragma unroll
            for (int cq = 0; cq < CT/4; cq++)
                *(float4*)&C[(size_t)(gr0+1)*NC + c0 + cq*4] =
                    make_float4(hi[cq*4], hi[cq*4+1], hi[cq*4+2], hi[cq*4+3]);
        }
    }
}

// ------------------------------ GAT layer 1 ---------------------------------
// fused: h1 = h1_partial0 + h1_partial1 (written back), then per-(node,head)
// attention logits es/ed.
__global__ void logits1_fused(const float* __restrict__ a_src, const float* __restrict__ a_dst, int n) {
    int i = blockIdx.x * blockDim.x + threadIdx.x;
    if (i < n*3) {
        int node = i / 3, h = i % 3;
        size_t base = (size_t)node*48 + h*16;
        float as[16];
        #pragma unroll
        for (int q = 0; q < 4; q++) {
            float4 a = *(const float4*)&g_h1[base + q*4];
            float4 b = *(const float4*)&g_h1b[base + q*4];
            float4 v = make_float4(a.x+b.x, a.y+b.y, a.z+b.z, a.w+b.w);
            *(float4*)&g_h1[base + q*4] = v;
            as[q*4+0]=v.x; as[q*4+1]=v.y; as[q*4+2]=v.z; as[q*4+3]=v.w;
        }
        float s = 0.f, d = 0.f;
        #pragma unroll
        for (int c = 0; c < 16; c++) {
            s += as[c] * a_src[h*16 + c];
            d += as[c] * a_dst[h*16 + c];
        }
        g_es1[i] = s;
        g_ed1[i] = d;
    }
}

// warp per node: softmax-attention aggregation (no max pass; see expw),
// fused norm + bias + ELU. Edge loop unrolled x2 for MLP.
__global__ void gat1_agg(const float* __restrict__ b1, int n) {
    int gw = (blockIdx.x * blockDim.x + threadIdx.x) >> 5;
    int lane = threadIdx.x & 31;
    if (gw >= n) return;
    int d = gw;
    int rp0 = g_rp[d], cnt = g_rp[d+1] - rp0;
    float ed0 = g_ed1[d*3+0], ed1 = g_ed1[d*3+1], ed2 = g_ed1[d*3+2];

    int ha = lane >> 4;
    float eda = ha ? ed1 : ed0;
    float acca = 0.f, accb = 0.f, ssa = 0.f, ssb = 0.f;
    int p = rp0, pend = rp0 + cnt;
    for (; p + 2 <= pend; p += 2) {
        int s0 = g_csrc[p], s1 = g_csrc[p+1];
        float la0 = g_es1[s0*3+ha], la1 = g_es1[s1*3+ha];
        float h0 = g_h1[s0*48 + lane], h1v = g_h1[s1*48 + lane];
        float wa0 = expw(leaky(la0 + eda));
        float wa1 = expw(leaky(la1 + eda));
        ssa += wa0 + wa1;
        acca += wa0 * h0 + wa1 * h1v;
        if (lane < 16) {
            float lb0 = g_es1[s0*3+2], lb1 = g_es1[s1*3+2];
            float hb0 = g_h1[s0*48 + 32 + lane], hb1 = g_h1[s1*48 + 32 + lane];
            float wb0 = expw(leaky(lb0 + ed2));
            float wb1 = expw(leaky(lb1 + ed2));
            ssb += wb0 + wb1;
            accb += wb0 * hb0 + wb1 * hb1;
        }
    }
    if (p < pend) {
        int s0 = g_csrc[p];
        float wa = expw(leaky(g_es1[s0*3+ha] + eda));
        ssa += wa;
        acca += wa * g_h1[s0*48 + lane];
        if (lane < 16) {
            float wb = expw(leaky(g_es1[s0*3+2] + ed2));
            ssb += wb;
            accb += wb * g_h1[s0*48 + 32 + lane];
        }
    }
    float va = acca / ssa + b1[lane];
    va = va > 0.f ? va : expm1f(va);
    g_acc1[d*48 + lane] = va;
    if (lane < 16) {
        float vb = accb / ssb + b1[32 + lane];
        vb = vb > 0.f ? vb : expm1f(vb);
        g_acc1[d*48 + 32 + lane] = vb;
    }
}

// ------------------------------ GAT layer 2 ---------------------------------
// one warp per node, float4 per lane (lane q covers channels 4q..4q+3)
__global__ void logits2(const float* __restrict__ a_src, const float* __restrict__ a_dst, int n) {
    int gid = blockIdx.x * blockDim.x + threadIdx.x;
    int node = gid >> 5;
    int lane = gid & 31;
    if (node < n) {
        float4 hv = *(const float4*)&g_h2[(size_t)node*128 + lane*4];
        float4 av = *(const float4*)&a_src[lane*4];
        float4 dv = *(const float4*)&a_dst[lane*4];
        float s = hv.x*av.x + hv.y*av.y + hv.z*av.z + hv.w*av.w;
        float d = hv.x*dv.x + hv.y*dv.y + hv.z*dv.z + hv.w*dv.w;
        #pragma unroll
        for (int o = 16; o > 0; o >>= 1) {
            s += __shfl_xor_sync(0xffffffffu, s, o);
            d += __shfl_xor_sync(0xffffffffu, d, o);
        }
        if (lane == 0) { g_es2[node] = s; g_ed2[node] = d; }
    }
}

// warp per node: GAT2 aggregation (no max pass) fused with bias +
// log_softmax(128), unroll x2
__global__ void gat2_agg(const float* __restrict__ b2, int n) {
    int gw = (blockIdx.x * blockDim.x + threadIdx.x) >> 5;
    int lane = threadIdx.x & 31;
    if (gw >= n) return;
    int d = gw;
    int rp0 = g_rp[d], cnt = g_rp[d+1] - rp0;
    float edv = g_ed2[d];

    float acc[4] = {0.f, 0.f, 0.f, 0.f};
    float ss = 0.f;
    int p = rp0, pend = rp0 + cnt;
    for (; p + 2 <= pend; p += 2) {
        int s0 = g_csrc[p], s1 = g_csrc[p+1];
        float e0 = g_es2[s0], e1 = g_es2[s1];
        const float* hp0 = g_h2 + (size_t)s0*128 + lane;
        const float* hp1 = g_h2 + (size_t)s1*128 + lane;
        float h0[4], h1[4];
        #pragma unroll
        for (int q = 0; q < 4; q++) { h0[q] = hp0[q*32]; h1[q] = hp1[q*32]; }
        float w0 = expw(leaky(e0 + edv));
        float w1 = expw(leaky(e1 + edv));
        ss += w0 + w1;
        #pragma unroll
        for (int q = 0; q < 4; q++) acc[q] += w0 * h0[q] + w1 * h1[q];
    }
    if (p < pend) {
        int s0 = g_csrc[p];
        float w = expw(leaky(g_es2[s0] + edv));
        ss += w;
        const float* hp = g_h2 + (size_t)s0*128 + lane;
        #pragma unroll
        for (int q = 0; q < 4; q++) acc[q] += w * hp[q*32];
    }

    float v[4];
    float inv = 1.0f / ss;
    #pragma unroll
    for (int q = 0; q < 4; q++) v[q] = acc[q] * inv + b2[lane + q*32];

    float lm = fmaxf(fmaxf(v[0], v[1]), fmaxf(v[2], v[3]));
    #pragma unroll
    for (int o = 16; o > 0; o >>= 1) lm = fmaxf(lm, __shfl_xor_sync(0xffffffffu, lm, o));
    float es = 0.f;
    #pragma unroll
    for (int q = 0; q < 4; q++) es += __expf(v[q] - lm);
    #pragma unroll
    for (int o = 16; o > 0; o >>= 1) es += __shfl_xor_sync(0xffffffffu, es, o);
    float lse = lm + logf(es);
    float* op = g_acc2 + (size_t)d*128 + lane;
    #pragma unroll
    for (int q = 0; q < 4; q++) op[q*32] = v[q] - lse;
}

// ------------------------------- GCN ----------------------------------------
// warp per node: normalized aggregation fused with bias + relu, unroll x2
__global__ void gcn_agg(const float* __restrict__ bg, int n) {
    int gw = (blockIdx.x * blockDim.x + threadIdx.x) >> 5;
    int lane = threadIdx.x & 31;
    if (gw >= n) return;
    int d = gw;
    int rp0 = g_rp[d], cnt = g_rp[d+1] - rp0;
    float dd = g_dinv[d];

    float acc[4] = {0.f, 0.f, 0.f, 0.f};
    int p = rp0, pend = rp0 + cnt;
    for (; p + 2 <= pend; p += 2) {
        int s0 = g_csrc[p], s1 = g_csrc[p+1];
        float n0 = g_dinv[s0] * dd, n1 = g_dinv[s1] * dd;
        const float* hp0 = g_hg + (size_t)s0*128 + lane;
        const float* hp1 = g_hg + (size_t)s1*128 + lane;
        float h0[4], h1[4];
        #pragma unroll
        for (int q = 0; q < 4; q++) { h0[q] = hp0[q*32]; h1[q] = hp1[q*32]; }
        #pragma unroll
        for (int q = 0; q < 4; q++) acc[q] += n0 * h0[q] + n1 * h1[q];
    }
    if (p < pend) {
        int s0 = g_csrc[p];
        float nrm = g_dinv[s0] * dd;
        const float* hp = g_hg + (size_t)s0*128 + lane;
        #pragma unroll
        for (int q = 0; q < 4; q++) acc[q] += nrm * hp[q*32];
    }
    float* op = g_accg + (size_t)d*128 + lane;
    #pragma unroll
    for (int q = 0; q < 4; q++) {
        float v = acc[q] + bg[lane + q*32];
        op[q*32] = v > 0.f ? v : 0.f;
    }
}

// ------------------------------ launch --------------------------------------
static inline int cdiv(int a, int b) { return (a + b - 1) / b; }

extern "C" void kernel_launch(void* const* d_in, const int* in_sizes, int n_in,
                              void* d_out, int out_size) {
    const float* x   = (const float*)d_in[0];
    const int*   ei  = (const int*)d_in[1];   // int32 view; dtype detected on device
    const float* W1  = (const float*)d_in[2];
    const float* as1 = (const float*)d_in[3];
    const float* ad1 = (const float*)d_in[4];
    const float* b1  = (const float*)d_in[5];
    const float* W2  = (const float*)d_in[6];
    const float* as2 = (const float*)d_in[7];
    const float* ad2 = (const float*)d_in[8];
    const float* b2  = (const float*)d_in[9];
    const float* Wg  = (const float*)d_in[10];
    const float* bg  = (const float*)d_in[11];
    const float* Wl  = (const float*)d_in[12];
    const float* bl  = (const float*)d_in[13];
    float*       out = (float*)d_out;

    int n  = in_sizes[0] / 512;
    int E  = in_sizes[1] / 2;
    int ET = E + n;
    if (ET > ETMAX) ET = ETMAX;

    int warps_grid = cdiv(n * 32, 256);
    int nb = cdiv(n, 2048);                   // scan blocks (25 for n=50000)

    zero_deg<<<cdiv(n,256),256>>>(ei, n);             // 1 (also dtype detect)
    count_deg<<<cdiv(ET,256),256>>>(ei, E, n);        // 2
    scan_block<<<nb,256>>>(n);                        // 3

    // GAT1 GEMM as 4th launch (ncu profiles launch #4)
    // CT=4 (192 thr), BK=64 (measured best), split-K x2
    gemm_kernel<512,48,128,64,4,2, 0,11><<<2*cdiv(n,128),192>>>(x, W1, nullptr, nullptr, n); // 4

    scan_partials<<<1,32>>>(nb, n);                   // 5
    scan_apply<<<nb,256>>>(n);                        // 6
    fill_csr<<<cdiv(ET,256),256>>>(ei, E, n);         // 7

    // --- GAT layer 1 (fused partial-reduce + logits) ---
    logits1_fused<<<cdiv(3*n,256),256>>>(as1, ad1, n);
    gat1_agg<<<warps_grid,256>>>(b1, n);

    // --- GAT layer 2 (+ log_softmax) ---
    gemm_kernel<48,128,64,48,8,1, 1,12><<<cdiv(n,64),128>>>(nullptr, W2, nullptr, nullptr, n);
    logits2<<<cdiv(32*n,256),256>>>(as2, ad2, n);
    gat2_agg<<<warps_grid,256>>>(b2, n);

    // --- GCN + relu (BK=64: measured win vs 32) ---
    gemm_kernel<128,128,64,64,8,1, 2,13><<<cdiv(n,64),128>>>(nullptr, Wg, nullptr, nullptr, n);
    gcn_agg<<<warps_grid,256>>>(bg, n);

    // --- final linear (BK=64) ---
    gemm_kernel<128,128,64,64,8,1, 3,0><<<cdiv(n,64),128>>>(nullptr, Wl, bl, out, n);
}